// round 6
// baseline (speedup 1.0000x reference)
#include <cuda_runtime.h>
#include <stdint.h>

// JeffressLinear: T=64, N=16, C=256, D=129, decay=exp(-1/2)
// Per output column (n,c,d): s_t = s_{t-1}*decay + w*(x0[(t-dly0)&63] + x1[(t-dly1)&63])
// dly_ch = min( stoch_round(relu(+/-delay_param[d])), 63 - argmax_t x_ch ) in [0,63].
//
// Block owns G=8 consecutive nc (slab = 1032 floats per t-plane, 258 float4).
// NT=576: threads 0..257 emit t in [0,32), threads 288..545 emit t in [32,64).
// Linearity: upper-half initial state = Fh0[dly0] + Fh1[dly1], where Fh is the
// per-(g,ch,dly) channel LIF state at t=31, precomputed by 512 threads.
// XT layout: doubled (i in [0,128)) and transposed-by-4: word(i)=(i&3)*32+(i>>2),
// pitch 132. Delays are ~linear in d (slope +/-1), so lanes (d stride 4) hit
// word-stride-1 -> (near) conflict-free; unrolled t folds into LDS immediates.

#define T_      64
#define N_      16
#define C_      256
#define D_      129
#define G_      8
#define SLAB    (G_ * D_)        // 1032
#define NV      (SLAB / 4)       // 258 vector threads per t-half
#define NT      576              // 18 warps
#define PITCH   132
#define DECAYF  0.60653065971263342f
#define TSTRIDE (N_ * C_ * D_)   // floats between consecutive t planes

__global__ __launch_bounds__(NT, 2) void jeff_kernel(
    const float* __restrict__ input,        // (T, N, C, 2)
    const float* __restrict__ delay_param,  // (D, 1)
    const float* __restrict__ weight,       // scalar
    const float* __restrict__ u,            // (N, C, D, 2)
    float* __restrict__ out)                // (T, N, C, D)
{
    __shared__ float XT[2 * G_ * PITCH];           // w-scaled, doubled, transposed series
    __shared__ __align__(16) uint32_t PK[SLAB];    // r0 | r1<<8 | g<<16 (unclamped)
    __shared__ float Fh[2 * G_ * 64];              // [gch][dly] channel state at t=31 (w-scaled)
    __shared__ int   LS[2 * G_];                   // 63 - spike_t per (g,ch)

    const int tid = threadIdx.x;
    const int nc0 = blockIdx.x * G_;
    const int n   = nc0 >> 8;
    const int c0  = nc0 & 255;
    const float w = __ldg(weight);

    // ---- Phase A1: load input (coalesced 64B segments), fill XT ----
    for (int j = tid; j < G_ * 2 * T_; j += NT) {
        const int t  = j >> 4;
        const int g  = (j >> 1) & 7;
        const int ch = j & 1;
        const float v = __ldg(&input[(((size_t)t * N_ + n) * C_ + (c0 + g)) * 2 + ch]) * w;
        const int base = (g * 2 + ch) * PITCH + ((t & 3) << 5) + (t >> 2);
        XT[base]      = v;                 // i = t
        XT[base + 16] = v;                 // i = t + 64
    }

    // ---- Phase A2: stochastically-rounded (unclamped) delays ----
    for (int j = tid; j < SLAB; j += NT) {
        const int g = (j * 8129) >> 20;    // j / 129 for j < 1032
        const int d = j - g * D_;
        const float dp = __ldg(&delay_param[d]);
        const float d0 = fmaxf(dp, 0.0f);
        const float d1 = fmaxf(-dp, 0.0f);
        const float f0 = floorf(d0);
        const float f1 = floorf(d1);
        const float2 uv = __ldg((const float2*)u + (size_t)(nc0 + g) * D_ + d);
        const int r0 = (int)f0 + ((uv.x < d0 - f0) ? 1 : 0);
        const int r1 = (int)f1 + ((uv.y < d1 - f1) ? 1 : 0);
        PK[j] = (uint32_t)r0 | ((uint32_t)r1 << 8) | ((uint32_t)g << 16);
    }
    __syncthreads();

    // ---- Phase B: Fh (mid states, tid<512) in parallel with argmax (tid>=512) ----
    if (tid < 512) {
        // two chains per thread: sid and sid+512; dly remapped so lanes stride 4
#pragma unroll
        for (int h = 0; h < 2; ++h) {
            const int sid = tid + h * 512;                 // [9:6]=gch(partial) [5:0]=raw
            const int gch = sid >> 6;
            const int dly = (((sid & 15) << 2) | ((sid >> 4) & 3));
            const int base = gch * PITCH;
            const int K = 64 - dly;                        // in [1,64]
            int A[4];
#pragma unroll
            for (int j = 0; j < 4; ++j) {
                const int i = K + j;
                A[j] = base + ((i & 3) << 5) + (i >> 2);
            }
            float v = 0.0f;
#pragma unroll
            for (int m = 0; m < 8; ++m) {
#pragma unroll
                for (int j = 0; j < 4; ++j)
                    v = v * DECAYF + XT[A[j] + m];         // t = 4m+j, up to t=31
            }
            Fh[gch * 64 + dly] = v;
        }
    } else {
        // first-argmax: 4 lanes per series (16 series), lanes ordered by t
        const int q   = tid - 512;                         // 0..63
        const int sid = q >> 2;                            // gch
        const int l4  = q & 3;
        const int base = sid * PITCH;
        float bv = -1.0f; int bi = 0;
#pragma unroll
        for (int k = 0; k < 16; ++k) {
            const int t = l4 * 16 + k;
            const float v = XT[base + ((t & 3) << 5) + (t >> 2)];
            if (v > bv) { bv = v; bi = t; }                // strict > -> FIRST max (w>0)
        }
#pragma unroll
        for (int off = 2; off > 0; off >>= 1) {
            const float ov = __shfl_down_sync(0xffffffffu, bv, off, 4);
            const int   oi = __shfl_down_sync(0xffffffffu, bi, off, 4);
            if (ov > bv) { bv = ov; bi = oi; }             // tie -> keep lower t
        }
        if (l4 == 0) LS[sid] = 63 - bi;
    }
    __syncthreads();

    // ---- Phase C: two t-halves, 4 interleaved recurrences/thread, STG.128 per t ----
    int vt = -1, tbase = 0;
    if (tid < NV)                        { vt = tid;       tbase = 0;  }
    else if (tid >= 288 && tid < 288+NV) { vt = tid - 288; tbase = 32; }

    if (vt >= 0) {
        const uint4 pkv = *(const uint4*)&PK[vt * 4];
        const uint32_t pks[4] = { pkv.x, pkv.y, pkv.z, pkv.w };

        int A0[4][4], A1[4][4];
        float s[4];
#pragma unroll
        for (int c = 0; c < 4; ++c) {
            const uint32_t pk = pks[c];
            const int g    = (int)(pk >> 16);
            const int dly0 = min((int)(pk & 0xff),        LS[2 * g]);
            const int dly1 = min((int)((pk >> 8) & 0xff), LS[2 * g + 1]);
            const int K0 = 64 - dly0 + tbase;              // i = K + (t - tbase)
            const int K1 = 64 - dly1 + tbase;
            const int b0 = (g * 2 + 0) * PITCH;
            const int b1 = (g * 2 + 1) * PITCH;
#pragma unroll
            for (int j = 0; j < 4; ++j) {
                const int i0 = K0 + j, i1 = K1 + j;
                A0[c][j] = b0 + ((i0 & 3) << 5) + (i0 >> 2);
                A1[c][j] = b1 + ((i1 & 3) << 5) + (i1 >> 2);
            }
            s[c] = (tbase == 0) ? 0.0f
                 : (Fh[(2 * g + 0) * 64 + dly0] + Fh[(2 * g + 1) * 64 + dly1]);
        }

        float s0 = s[0], s1 = s[1], s2 = s[2], s3 = s[3];
        float* op = out + (size_t)nc0 * D_ + vt * 4 + (size_t)tbase * TSTRIDE;

#pragma unroll
        for (int m = 0; m < 8; ++m) {
#pragma unroll
            for (int j = 0; j < 4; ++j) {                  // all LDS offsets fold to immediates
                float4 v;
                v.x = s0 = s0 * DECAYF + (XT[A0[0][j] + m] + XT[A1[0][j] + m]);
                v.y = s1 = s1 * DECAYF + (XT[A0[1][j] + m] + XT[A1[1][j] + m]);
                v.z = s2 = s2 * DECAYF + (XT[A0[2][j] + m] + XT[A1[2][j] + m]);
                v.w = s3 = s3 * DECAYF + (XT[A0[3][j] + m] + XT[A1[3][j] + m]);
                *(float4*)op = v;
                op += TSTRIDE;
            }
        }
    }
}

extern "C" void kernel_launch(void* const* d_in, const int* in_sizes, int n_in,
                              void* d_out, int out_size) {
    const float* input       = (const float*)d_in[0];
    const float* delay_param = (const float*)d_in[1];
    const float* weight      = (const float*)d_in[2];
    const float* u           = (const float*)d_in[3];
    float* out = (float*)d_out;

    jeff_kernel<<<(N_ * C_) / G_, NT>>>(input, delay_param, weight, u, out);
}